// round 2
// baseline (speedup 1.0000x reference)
#include <cuda_runtime.h>
#include <math.h>

#define N_NODES 2048
#define IN_F    128
#define OUT_F   32
#define NEG_INF (-9e15f)

// Kernel-2 tiling
#define KC      512        // k-chunk held in smem
#define ROWS    16         // rows (warps) per CTA
#define NSTEP   (KC / 32)

// Scratch (allocation-free rule: __device__ globals)
__device__ float g_Wh1[N_NODES * OUT_F];
__device__ float g_Wh2[N_NODES * OUT_F];
__device__ float g_c6[N_NODES];   // 0.6 * sum_f a_f * Wh1[i,f]
__device__ float g_dk6[N_NODES];  // 0.6 * sum_f a_f * Wh2[k,f]

// ---------------------------------------------------------------------------
// Kernel 1: Wh1 = h @ W[:128], Wh2 = h @ W[128:], plus row dot-products with a.
// CTA: (32 features, 8 rows). W cached in smem (32KB), h rows in smem (4KB).
// ---------------------------------------------------------------------------
__global__ __launch_bounds__(256) void gat_gemm_kernel(
    const float* __restrict__ h,
    const float* __restrict__ W,
    const float* __restrict__ a)
{
    __shared__ float Ws[2 * IN_F * OUT_F];  // 8192 floats = 32 KB
    __shared__ float hs[8][IN_F];           // 4 KB

    const int tx = threadIdx.x;            // feature 0..31
    const int ty = threadIdx.y;            // row-in-block 0..7
    const int tid = ty * 32 + tx;
    const int row0 = blockIdx.x * 8;

    // Cooperative loads (float4, coalesced)
    for (int i = tid; i < (2 * IN_F * OUT_F) / 4; i += 256)
        ((float4*)Ws)[i] = ((const float4*)W)[i];
    for (int i = tid; i < (8 * IN_F) / 4; i += 256)
        ((float4*)&hs[0][0])[i] = ((const float4*)(h + (size_t)row0 * IN_F))[i];
    __syncthreads();

    float wh1 = 0.f, wh2 = 0.f;
#pragma unroll 8
    for (int j = 0; j < IN_F; ++j) {
        float hv = hs[ty][j];                         // broadcast across lanes
        wh1 = fmaf(hv, Ws[j * OUT_F + tx], wh1);      // conflict-free
        wh2 = fmaf(hv, Ws[(IN_F + j) * OUT_F + tx], wh2);
    }

    const int row = row0 + ty;
    g_Wh1[row * OUT_F + tx] = wh1;
    g_Wh2[row * OUT_F + tx] = wh2;

    float av = a[tx];
    float c = av * wh1;
    float d = av * wh2;
#pragma unroll
    for (int off = 16; off; off >>= 1) {
        c += __shfl_xor_sync(0xffffffffu, c, off);
        d += __shfl_xor_sync(0xffffffffu, d, off);
    }
    if (tx == 0) {
        g_c6[row]  = 0.6f * c;
        g_dk6[row] = 0.6f * d;
    }
}

// ---------------------------------------------------------------------------
// Kernel 2: fused score + masked online-softmax + aggregation + ELU.
// One warp per output row; each lane owns k = lane, lane+32, ... (64 values).
// e[i,k] = c6_i + dk6_k + sum_f (0.4 a_f)|Wh1[i,f] + Wh2[k,f]|
// Smem tiles of Wh2/Wh1 are XOR-swizzled per float4 for conflict-free LDS.128.
// ---------------------------------------------------------------------------
extern __shared__ float smem2[];

__global__ __launch_bounds__(512, 1) void gat_attn_kernel(
    const int*   __restrict__ adj,
    const float* __restrict__ a,
    float*       __restrict__ out)
{
    float4* s_wh2 = (float4*)smem2;                      // KC*8 float4 (64 KB)
    float4* s_wh1 = (float4*)(smem2 + KC * OUT_F);       // KC*8 float4 (64 KB)
    float*  s_dk6 = smem2 + 2 * KC * OUT_F;              // KC floats  (2 KB)

    const int tid  = threadIdx.x;
    const int w    = tid >> 5;
    const int lane = tid & 31;
    const int row  = blockIdx.x * ROWS + w;

    // Per-lane register constants: a4[f] = 0.4*a[f], wh1i[f] = Wh1[row,f]
    float a4[OUT_F], wh1i[OUT_F], acc[OUT_F];
#pragma unroll
    for (int f = 0; f < OUT_F; ++f) {
        a4[f]   = 0.4f * __ldg(&a[f]);
        wh1i[f] = g_Wh1[row * OUT_F + f];
        acc[f]  = 0.f;
    }
    const float c6i = g_c6[row];

    float m = NEG_INF;      // running max (NEG_INF init reproduces masked-row semantics)
    float lsum = 0.f;       // running denominator

    const int* adj_row = adj + (size_t)row * N_NODES;
    int adj_next = adj_row[lane];                         // prefetch k = lane

    for (int kt = 0; kt < N_NODES; kt += KC) {
        __syncthreads();
        // Cooperative swizzled tile load (coalesced float4 from L2)
        for (int i = tid; i < KC * 8; i += 512) {
            int kk = i >> 3;
            int f4 = i & 7;
            int sidx = (kk << 3) | (f4 ^ (kk & 7));
            int gidx = ((kt + kk) << 3) | f4;
            s_wh2[sidx] = ((const float4*)g_Wh2)[gidx];
            s_wh1[sidx] = ((const float4*)g_Wh1)[gidx];
        }
        for (int i = tid; i < KC; i += 512) s_dk6[i] = g_dk6[kt + i];
        __syncthreads();

#pragma unroll 1
        for (int step = 0; step < NSTEP; ++step) {
            const int kk = (step << 5) | lane;            // index within tile
            const int adjv = adj_next;
            // one-ahead prefetch of adjacency (global k + 32), clamped at end
            int knext = kt + ((step + 1) << 5) + lane;
            if (knext >= N_NODES) knext = 0;
            adj_next = adj_row[knext];

            const int sbase = kk << 3;
            const int sx    = kk & 7;

            // Score: s2 = sum_f a4_f * |wh1i_f + wh2_kf|   (FADD + FFMA.|.| per f)
            float s2 = 0.f;
#pragma unroll
            for (int f4 = 0; f4 < 8; ++f4) {
                float4 v = s_wh2[sbase | (f4 ^ sx)];
                float x0 = wh1i[4 * f4 + 0] + v.x;
                float x1 = wh1i[4 * f4 + 1] + v.y;
                float x2 = wh1i[4 * f4 + 2] + v.z;
                float x3 = wh1i[4 * f4 + 3] + v.w;
                s2 = fmaf(a4[4 * f4 + 0], fabsf(x0), s2);
                s2 = fmaf(a4[4 * f4 + 1], fabsf(x1), s2);
                s2 = fmaf(a4[4 * f4 + 2], fabsf(x2), s2);
                s2 = fmaf(a4[4 * f4 + 3], fabsf(x3), s2);
            }
            const float e = (adjv > 0) ? (c6i + s_dk6[kk] + s2) : NEG_INF;

            // Branchless online softmax (per-lane state)
            const float mnew  = fmaxf(m, e);
            const float scale = __expf(m - mnew);   // 1.0 when m == mnew (incl. both NEG_INF)
            const float p     = __expf(e - mnew);
            m = mnew;
            lsum = fmaf(lsum, scale, p);

            // Aggregate p * Wh1[k,:] with rescale folded into one FFMA per f
#pragma unroll
            for (int f4 = 0; f4 < 8; ++f4) {
                float4 v = s_wh1[sbase | (f4 ^ sx)];
                acc[4 * f4 + 0] = fmaf(acc[4 * f4 + 0], scale, p * v.x);
                acc[4 * f4 + 1] = fmaf(acc[4 * f4 + 1], scale, p * v.y);
                acc[4 * f4 + 2] = fmaf(acc[4 * f4 + 2], scale, p * v.z);
                acc[4 * f4 + 3] = fmaf(acc[4 * f4 + 3], scale, p * v.w);
            }
        }
    }

    // ---- Cross-lane combine ----
    float mg = m;
#pragma unroll
    for (int off = 16; off; off >>= 1)
        mg = fmaxf(mg, __shfl_xor_sync(0xffffffffu, mg, off));
    const float cs = __expf(m - mg);
    float L = lsum * cs;
#pragma unroll
    for (int off = 16; off; off >>= 1)
        L += __shfl_xor_sync(0xffffffffu, L, off);

    __syncthreads();  // tiles no longer needed by any warp -> reuse smem
    float* red = smem2 + w * (32 * 33);   // 16 warps * 4224 B = 67.6 KB < 130 KB
#pragma unroll
    for (int f = 0; f < OUT_F; ++f)
        red[lane * 33 + f] = acc[f] * cs;
    __syncwarp();

    float tot = 0.f;
#pragma unroll 8
    for (int j = 0; j < 32; ++j)
        tot += red[j * 33 + lane];        // conflict-free (pad 33)

    const float hv = tot / L;
    out[row * OUT_F + lane] = hv > 0.f ? hv : expm1f(hv);  // ELU
}

// ---------------------------------------------------------------------------
// Launch
// ---------------------------------------------------------------------------
extern "C" void kernel_launch(void* const* d_in, const int* in_sizes, int n_in,
                              void* d_out, int out_size)
{
    const float* h   = (const float*)d_in[0];   // [2048,128] f32
    const int*   adj = (const int*)  d_in[1];   // [2048,2048] i32
    const float* W   = (const float*)d_in[2];   // [256,32] f32
    const float* a   = (const float*)d_in[3];   // [32] f32
    float*       out = (float*)d_out;           // [2048,32] f32

    gat_gemm_kernel<<<N_NODES / 8, dim3(32, 8)>>>(h, W, a);

    const int smem_bytes = (2 * KC * OUT_F + KC) * (int)sizeof(float);  // 133120
    static int attr_set = 0;
    cudaFuncSetAttribute(gat_attn_kernel,
                         cudaFuncAttributeMaxDynamicSharedMemorySize, smem_bytes);
    (void)attr_set;
    gat_attn_kernel<<<N_NODES / ROWS, 512, smem_bytes>>>(adj, a, out);
}

// round 4
// speedup vs baseline: 1.0396x; 1.0396x over previous
#include <cuda_runtime.h>
#include <math.h>
#include <stdint.h>

#define N_NODES 2048
#define IN_F    128
#define OUT_F   32
#define KC      256
#define NTILES  (N_NODES / KC)          // 8
#define NSTEP   (KC / 32)               // 8
#define WARPS   7
#define THREADS (WARPS * 32)            // 224
#define GRID    147                     // 147*14 = 2058 >= 2048 rows
#define STAGE_FLOATS (2 * KC * OUT_F + KC)
#define STAGE_BYTES  (STAGE_FLOATS * 4)      // 66560
#define SMEM_BYTES   (2 * STAGE_BYTES)       // 133120
#define LOG2E 1.4426950408889634f
#define ABS2  0x7fffffff7fffffffull

__device__ float    g_Wh1[N_NODES * OUT_F];   // raw Wh1 (aggregation)
__device__ float    g_Wh2s[N_NODES * OUT_F];  // 0.4*log2e*a_f * Wh2 (score)
__device__ float    g_c6L[N_NODES];           // log2e*0.6*sum_f a_f*Wh1[i,f]
__device__ float    g_dk6L[N_NODES];          // log2e*0.6*sum_f a_f*Wh2[k,f]
__device__ unsigned g_adjbits[N_NODES * (N_NODES / 32)];

// ---------------------------------------------------------------------------
// Kernel 1: projections + pre-scaled score operand + per-row constants
// ---------------------------------------------------------------------------
__global__ __launch_bounds__(256) void gat_gemm_kernel(
    const float* __restrict__ h, const float* __restrict__ W,
    const float* __restrict__ a)
{
    __shared__ float Ws[2 * IN_F * OUT_F];
    __shared__ float hs[8][IN_F];
    const int tx = threadIdx.x, ty = threadIdx.y;
    const int tid = ty * 32 + tx;
    const int row0 = blockIdx.x * 8;

    for (int i = tid; i < (2 * IN_F * OUT_F) / 4; i += 256)
        ((float4*)Ws)[i] = ((const float4*)W)[i];
    for (int i = tid; i < (8 * IN_F) / 4; i += 256)
        ((float4*)&hs[0][0])[i] = ((const float4*)(h + (size_t)row0 * IN_F))[i];
    __syncthreads();

    float wh1 = 0.f, wh2 = 0.f;
#pragma unroll 8
    for (int j = 0; j < IN_F; ++j) {
        float hv = hs[ty][j];
        wh1 = fmaf(hv, Ws[j * OUT_F + tx], wh1);
        wh2 = fmaf(hv, Ws[(IN_F + j) * OUT_F + tx], wh2);
    }
    const int row = row0 + ty;
    const float av = a[tx];
    g_Wh1[row * OUT_F + tx]  = wh1;
    g_Wh2s[row * OUT_F + tx] = (0.4f * LOG2E) * av * wh2;

    float c = av * wh1, d = av * wh2;
#pragma unroll
    for (int off = 16; off; off >>= 1) {
        c += __shfl_xor_sync(0xffffffffu, c, off);
        d += __shfl_xor_sync(0xffffffffu, d, off);
    }
    if (tx == 0) {
        g_c6L[row]  = (0.6f * LOG2E) * c;
        g_dk6L[row] = (0.6f * LOG2E) * d;
    }
}

// ---------------------------------------------------------------------------
// Kernel 1b: pack adjacency to bitmask (word w bit j = adj[row][32w+j] > 0)
// ---------------------------------------------------------------------------
__global__ __launch_bounds__(512) void pack_adj_kernel(const int* __restrict__ adj)
{
    const int w = threadIdx.x >> 5, lane = threadIdx.x & 31;
    const int row = blockIdx.x * 16 + w;
    const int* arow = adj + (size_t)row * N_NODES;
#pragma unroll 4
    for (int wi = 0; wi < 64; ++wi) {
        int v = __ldg(arow + wi * 32 + lane);
        unsigned b = __ballot_sync(0xffffffffu, v > 0);
        if (lane == 0) g_adjbits[row * 64 + wi] = b;
    }
}

// ---------------------------------------------------------------------------
// Kernel 2: fused score + masked softmax (no max-shift) + aggregation + ELU
// ---------------------------------------------------------------------------
extern __shared__ float smem2[];

__device__ __forceinline__ void issue_tile(int t, uint32_t smem_u, int tid)
{
    const int stage = t & 1;
    const uint32_t w2b = smem_u + stage * STAGE_BYTES;
    const uint32_t w1b = w2b + KC * OUT_F * 4;
    const uint32_t dkb = w2b + 2 * KC * OUT_F * 4;
    const float4* g2 = ((const float4*)g_Wh2s) + t * (KC * 8);
    const float4* g1 = ((const float4*)g_Wh1)  + t * (KC * 8);
    for (int i = tid; i < KC * 8; i += THREADS) {
        int kk = i >> 3, f4 = i & 7;
        uint32_t soff = (uint32_t)(((kk << 3) | (f4 ^ (kk & 7))) << 4);
        asm volatile("cp.async.cg.shared.global [%0], [%1], 16;"
                     :: "r"(w2b + soff), "l"(g2 + i) : "memory");
        asm volatile("cp.async.cg.shared.global [%0], [%1], 16;"
                     :: "r"(w1b + soff), "l"(g1 + i) : "memory");
    }
    const float* gd = g_dk6L + t * KC;
    for (int i = tid; i < KC; i += THREADS)
        asm volatile("cp.async.ca.shared.global [%0], [%1], 4;"
                     :: "r"(dkb + (uint32_t)(i * 4)), "l"(gd + i) : "memory");
    asm volatile("cp.async.commit_group;" ::: "memory");
}

__global__ __launch_bounds__(THREADS, 1) void gat_attn_kernel(
    const float* __restrict__ a, float* __restrict__ out)
{
    const int tid = threadIdx.x, w = tid >> 5, lane = tid & 31;
    const uint32_t smem_u = (uint32_t)__cvta_generic_to_shared(smem2);
    int row0 = blockIdx.x * 14 + 2 * w;
    int row1 = row0 + 1;
    if (row1 >= N_NODES) { row0 = N_NODES - 2; row1 = N_NODES - 1; }

    unsigned long long swh1[2][16], acc[2][16], sig[16];
#pragma unroll
    for (int j = 0; j < 16; ++j) {
        float a0 = __ldg(a + 2 * j), a1 = __ldg(a + 2 * j + 1);
        sig[j] = (unsigned long long)(__float_as_uint(a0) & 0x80000000u)
               | ((unsigned long long)(__float_as_uint(a1) & 0x80000000u) << 32);
        float A0 = (0.4f * LOG2E) * a0, A1 = (0.4f * LOG2E) * a1;
        float x0 = A0 * g_Wh1[row0 * OUT_F + 2 * j];
        float x1 = A1 * g_Wh1[row0 * OUT_F + 2 * j + 1];
        float y0 = A0 * g_Wh1[row1 * OUT_F + 2 * j];
        float y1 = A1 * g_Wh1[row1 * OUT_F + 2 * j + 1];
        asm("mov.b64 %0, {%1, %2};" : "=l"(swh1[0][j]) : "f"(x0), "f"(x1));
        asm("mov.b64 %0, {%1, %2};" : "=l"(swh1[1][j]) : "f"(y0), "f"(y1));
        acc[0][j] = 0ull; acc[1][j] = 0ull;
    }
    const float c0 = g_c6L[row0], c1 = g_c6L[row1];
    float lsum0 = 0.f, lsum1 = 0.f;
    const unsigned* bits0 = g_adjbits + row0 * 64;
    const unsigned* bits1 = g_adjbits + row1 * 64;

    issue_tile(0, smem_u, tid);

#pragma unroll 1
    for (int t = 0; t < NTILES; ++t) {
        __syncthreads();
        if (t + 1 < NTILES) {
            issue_tile(t + 1, smem_u, tid);
            asm volatile("cp.async.wait_group 1;" ::: "memory");
        } else {
            asm volatile("cp.async.wait_group 0;" ::: "memory");
        }
        __syncthreads();

        const int stage = t & 1;
        const uint32_t w2b = smem_u + stage * STAGE_BYTES;
        const uint32_t w1b = w2b + KC * OUT_F * 4;
        const float* sdk = smem2 + stage * STAGE_FLOATS + 2 * KC * OUT_F;

#pragma unroll 1
        for (int step = 0; step < NSTEP; ++step) {
            const int kk = (step << 5) | lane;
            const unsigned mw0 = __ldg(bits0 + t * NSTEP + step);
            const unsigned mw1 = __ldg(bits1 + t * NSTEP + step);
            const float dkv = sdk[kk];
            const uint32_t rb2 = w2b + (uint32_t)(kk << 7);
            const uint32_t rb1 = w1b + (uint32_t)(kk << 7);
            const int sx = kk & 7;

            unsigned long long s0a = 0ull, s0b = 0ull, s1a = 0ull, s1b = 0ull;
#pragma unroll
            for (int f4 = 0; f4 < 8; ++f4) {
                unsigned long long v0, v1, u;
                asm volatile("ld.shared.v2.b64 {%0, %1}, [%2];"
                             : "=l"(v0), "=l"(v1) : "r"(rb2 + (uint32_t)((f4 ^ sx) << 4)));
                const int j0 = 2 * f4, j1 = 2 * f4 + 1;
                asm("add.rn.f32x2 %0, %1, %2;" : "=l"(u) : "l"(swh1[0][j0]), "l"(v0));
                u = (u & ABS2) ^ sig[j0];
                asm("add.rn.f32x2 %0, %0, %1;" : "+l"(s0a) : "l"(u));
                asm("add.rn.f32x2 %0, %1, %2;" : "=l"(u) : "l"(swh1[0][j1]), "l"(v1));
                u = (u & ABS2) ^ sig[j1];
                asm("add.rn.f32x2 %0, %0, %1;" : "+l"(s0b) : "l"(u));
                asm("add.rn.f32x2 %0, %1, %2;" : "=l"(u) : "l"(swh1[1][j0]), "l"(v0));
                u = (u & ABS2) ^ sig[j0];
                asm("add.rn.f32x2 %0, %0, %1;" : "+l"(s1a) : "l"(u));
                asm("add.rn.f32x2 %0, %1, %2;" : "=l"(u) : "l"(swh1[1][j1]), "l"(v1));
                u = (u & ABS2) ^ sig[j1];
                asm("add.rn.f32x2 %0, %0, %1;" : "+l"(s1b) : "l"(u));
            }

            float p0, p1;
            {
                unsigned long long ts; float lo, hi, e;
                asm("add.rn.f32x2 %0, %1, %2;" : "=l"(ts) : "l"(s0a), "l"(s0b));
                asm("mov.b64 {%0, %1}, %2;" : "=f"(lo), "=f"(hi) : "l"(ts));
                e = (c0 + dkv) + (lo + hi);
                asm("ex2.approx.f32 %0, %1;" : "=f"(p0) : "f"(e));
                p0 = ((mw0 >> lane) & 1u) ? p0 : 0.f;
                asm("add.rn.f32x2 %0, %1, %2;" : "=l"(ts) : "l"(s1a), "l"(s1b));
                asm("mov.b64 {%0, %1}, %2;" : "=f"(lo), "=f"(hi) : "l"(ts));
                e = (c1 + dkv) + (lo + hi);
                asm("ex2.approx.f32 %0, %1;" : "=f"(p1) : "f"(e));
                p1 = ((mw1 >> lane) & 1u) ? p1 : 0.f;
            }
            lsum0 += p0; lsum1 += p1;
            unsigned long long p20, p21;
            asm("mov.b64 %0, {%1, %1};" : "=l"(p20) : "f"(p0));
            asm("mov.b64 %0, {%1, %1};" : "=l"(p21) : "f"(p1));

#pragma unroll
            for (int f4 = 0; f4 < 8; ++f4) {
                unsigned long long v0, v1;
                asm volatile("ld.shared.v2.b64 {%0, %1}, [%2];"
                             : "=l"(v0), "=l"(v1) : "r"(rb1 + (uint32_t)((f4 ^ sx) << 4)));
                asm("fma.rn.f32x2 %0, %1, %2, %0;" : "+l"(acc[0][2*f4])   : "l"(p20), "l"(v0));
                asm("fma.rn.f32x2 %0, %1, %2, %0;" : "+l"(acc[0][2*f4+1]) : "l"(p20), "l"(v1));
                asm("fma.rn.f32x2 %0, %1, %2, %0;" : "+l"(acc[1][2*f4])   : "l"(p21), "l"(v0));
                asm("fma.rn.f32x2 %0, %1, %2, %0;" : "+l"(acc[1][2*f4+1]) : "l"(p21), "l"(v1));
            }
        }
    }

    // ---- Epilogue: cross-lane reduce, divide, ELU ----
    float L0 = lsum0, L1 = lsum1;
#pragma unroll
    for (int o = 16; o; o >>= 1) {
        L0 += __shfl_xor_sync(0xffffffffu, L0, o);
        L1 += __shfl_xor_sync(0xffffffffu, L1, o);
    }
    __syncthreads();                       // tile stages no longer needed
    float* red = smem2 + w * (32 * 33);
#pragma unroll 1
    for (int r = 0; r < 2; ++r) {
#pragma unroll
        for (int j = 0; j < 16; ++j) {
            float lo, hi;
            asm("mov.b64 {%0, %1}, %2;" : "=f"(lo), "=f"(hi) : "l"(acc[r][j]));
            red[lane * 33 + 2 * j]     = lo;
            red[lane * 33 + 2 * j + 1] = hi;
        }
        __syncwarp();
        float tot = 0.f;
#pragma unroll 8
        for (int jj = 0; jj < 32; ++jj) tot += red[jj * 33 + lane];
        const float L = r ? L1 : L0;
        const int row = r ? row1 : row0;
        const float hv = tot / L;
        out[row * OUT_F + lane] = hv > 0.f ? hv : expm1f(hv);
        __syncwarp();
    }
}

// ---------------------------------------------------------------------------
extern "C" void kernel_launch(void* const* d_in, const int* in_sizes, int n_in,
                              void* d_out, int out_size)
{
    const float* h   = (const float*)d_in[0];
    const int*   adj = (const int*)  d_in[1];
    const float* W   = (const float*)d_in[2];
    const float* a   = (const float*)d_in[3];
    float*       out = (float*)d_out;

    gat_gemm_kernel<<<N_NODES / 8, dim3(32, 8)>>>(h, W, a);
    pack_adj_kernel<<<N_NODES / 16, 512>>>(adj);

    cudaFuncSetAttribute(gat_attn_kernel,
                         cudaFuncAttributeMaxDynamicSharedMemorySize, SMEM_BYTES);
    gat_attn_kernel<<<GRID, THREADS, SMEM_BYTES>>>(a, out);
}

// round 5
// speedup vs baseline: 1.2273x; 1.1806x over previous
#include <cuda_runtime.h>
#include <math.h>
#include <stdint.h>

#define N_NODES 2048
#define IN_F    128
#define OUT_F   32
#define KC      256
#define NTILES  (N_NODES / KC)          // 8
#define NSTEP   (KC / 32)               // 8
#define WARPS   7
#define THREADS (WARPS * 32)            // 224
#define GRID    147                     // 147*14 = 2058 >= 2048 rows
#define STAGE_FLOATS (2 * KC * OUT_F + KC)
#define STAGE_BYTES  (STAGE_FLOATS * 4)      // 66560
#define SMEM_BYTES   (2 * STAGE_BYTES)       // 133120
#define LOG2E 1.4426950408889634f
#define ABS2  0x7fffffff7fffffffull

__device__ float g_Wh1[N_NODES * OUT_F];   // raw Wh1
__device__ float g_Wh2[N_NODES * OUT_F];   // raw Wh2
__device__ float g_c6L[N_NODES];           // log2e*0.6*sum_f a_f*Wh1[i,f]
__device__ float g_dk6L[N_NODES];          // log2e*0.6*sum_f a_f*Wh2[k,f]

// ---------------------------------------------------------------------------
// Kernel 1: projections + per-row dot constants. 128 CTAs x 16 rows.
// ---------------------------------------------------------------------------
__global__ __launch_bounds__(256) void gat_gemm_kernel(
    const float* __restrict__ h, const float* __restrict__ W,
    const float* __restrict__ a)
{
    __shared__ float Ws[2 * IN_F * OUT_F];  // 32 KB
    __shared__ float hs[16][IN_F];          // 8 KB
    const int tx = threadIdx.x, ty = threadIdx.y;   // (32, 8)
    const int tid = ty * 32 + tx;
    const int row0 = blockIdx.x * 16;

    for (int i = tid; i < (2 * IN_F * OUT_F) / 4; i += 256)
        ((float4*)Ws)[i] = ((const float4*)W)[i];
    for (int i = tid; i < (16 * IN_F) / 4; i += 256)
        ((float4*)&hs[0][0])[i] = ((const float4*)(h + (size_t)row0 * IN_F))[i];
    __syncthreads();

    float w1A = 0.f, w2A = 0.f, w1B = 0.f, w2B = 0.f;
#pragma unroll 4
    for (int j = 0; j < IN_F; ++j) {
        const float s1 = Ws[j * OUT_F + tx];
        const float s2 = Ws[(IN_F + j) * OUT_F + tx];
        const float hA = hs[ty][j];
        const float hB = hs[ty + 8][j];
        w1A = fmaf(hA, s1, w1A);  w2A = fmaf(hA, s2, w2A);
        w1B = fmaf(hB, s1, w1B);  w2B = fmaf(hB, s2, w2B);
    }

    const int rowA = row0 + ty, rowB = row0 + ty + 8;
    const float av = a[tx];
    g_Wh1[rowA * OUT_F + tx] = w1A;  g_Wh2[rowA * OUT_F + tx] = w2A;
    g_Wh1[rowB * OUT_F + tx] = w1B;  g_Wh2[rowB * OUT_F + tx] = w2B;

    float cA = av * w1A, dA = av * w2A, cB = av * w1B, dB = av * w2B;
#pragma unroll
    for (int off = 16; off; off >>= 1) {
        cA += __shfl_xor_sync(0xffffffffu, cA, off);
        dA += __shfl_xor_sync(0xffffffffu, dA, off);
        cB += __shfl_xor_sync(0xffffffffu, cB, off);
        dB += __shfl_xor_sync(0xffffffffu, dB, off);
    }
    if (tx == 0) {
        g_c6L[rowA]  = (0.6f * LOG2E) * cA;
        g_dk6L[rowA] = (0.6f * LOG2E) * dA;
        g_c6L[rowB]  = (0.6f * LOG2E) * cB;
        g_dk6L[rowB] = (0.6f * LOG2E) * dB;
    }
}

// ---------------------------------------------------------------------------
// Kernel 2: fused score + masked softmax (no max-shift) + aggregation + ELU.
// 2 rows per lane; adjacency prefetched one tile ahead into registers.
// ---------------------------------------------------------------------------
extern __shared__ float smem2[];

__device__ __forceinline__ void issue_tile(int t, uint32_t smem_u, int tid)
{
    const int stage = t & 1;
    const uint32_t w2b = smem_u + stage * STAGE_BYTES;
    const uint32_t w1b = w2b + KC * OUT_F * 4;
    const uint32_t dkb = w2b + 2 * KC * OUT_F * 4;
    const float4* g2 = ((const float4*)g_Wh2) + t * (KC * 8);
    const float4* g1 = ((const float4*)g_Wh1) + t * (KC * 8);
    for (int i = tid; i < KC * 8; i += THREADS) {
        int kk = i >> 3, f4 = i & 7;
        uint32_t soff = (uint32_t)(((kk << 3) | (f4 ^ (kk & 7))) << 4);
        asm volatile("cp.async.cg.shared.global [%0], [%1], 16;"
                     :: "r"(w2b + soff), "l"(g2 + i) : "memory");
        asm volatile("cp.async.cg.shared.global [%0], [%1], 16;"
                     :: "r"(w1b + soff), "l"(g1 + i) : "memory");
    }
    const float* gd = g_dk6L + t * KC;
    for (int i = tid; i < KC; i += THREADS)
        asm volatile("cp.async.ca.shared.global [%0], [%1], 4;"
                     :: "r"(dkb + (uint32_t)(i * 4)), "l"(gd + i) : "memory");
    asm volatile("cp.async.commit_group;" ::: "memory");
}

__global__ __launch_bounds__(THREADS, 1) void gat_attn_kernel(
    const int* __restrict__ adj, const float* __restrict__ a,
    float* __restrict__ out)
{
    const int tid = threadIdx.x, w = tid >> 5, lane = tid & 31;
    const uint32_t smem_u = (uint32_t)__cvta_generic_to_shared(smem2);
    int row0 = blockIdx.x * 14 + 2 * w;
    int row1 = row0 + 1;
    if (row1 >= N_NODES) { row0 = N_NODES - 2; row1 = N_NODES - 1; }

    // wh1p: raw Wh1 of both rows (packed), a4L: packed 0.4*log2e*a, acc: packed
    unsigned long long wh1p[2][16], acc[2][16], a4L[16];
#pragma unroll
    for (int j = 0; j < 16; ++j) {
        float a0 = __ldg(a + 2 * j), a1 = __ldg(a + 2 * j + 1);
        float A0 = (0.4f * LOG2E) * a0, A1 = (0.4f * LOG2E) * a1;
        float x0 = g_Wh1[row0 * OUT_F + 2 * j], x1 = g_Wh1[row0 * OUT_F + 2 * j + 1];
        float y0 = g_Wh1[row1 * OUT_F + 2 * j], y1 = g_Wh1[row1 * OUT_F + 2 * j + 1];
        asm("mov.b64 %0, {%1, %2};" : "=l"(a4L[j])    : "f"(A0), "f"(A1));
        asm("mov.b64 %0, {%1, %2};" : "=l"(wh1p[0][j]) : "f"(x0), "f"(x1));
        asm("mov.b64 %0, {%1, %2};" : "=l"(wh1p[1][j]) : "f"(y0), "f"(y1));
        acc[0][j] = 0ull; acc[1][j] = 0ull;
    }
    const float c0 = g_c6L[row0], c1 = g_c6L[row1];
    float lsum0 = 0.f, lsum1 = 0.f;

    const int* adjr0 = adj + (size_t)row0 * N_NODES;
    const int* adjr1 = adj + (size_t)row1 * N_NODES;

    // Adjacency values for the CURRENT tile, one register per step.
    int am0[NSTEP], am1[NSTEP];
#pragma unroll
    for (int s = 0; s < NSTEP; ++s) {
        am0[s] = __ldg(adjr0 + (s << 5) + lane);
        am1[s] = __ldg(adjr1 + (s << 5) + lane);
    }

    issue_tile(0, smem_u, tid);

#pragma unroll 1
    for (int t = 0; t < NTILES; ++t) {
        __syncthreads();
        if (t + 1 < NTILES) {
            issue_tile(t + 1, smem_u, tid);
            asm volatile("cp.async.wait_group 1;" ::: "memory");
        } else {
            asm volatile("cp.async.wait_group 0;" ::: "memory");
        }
        __syncthreads();

        const int stage = t & 1;
        const uint32_t w2b = smem_u + stage * STAGE_BYTES;
        const uint32_t w1b = w2b + KC * OUT_F * 4;
        const float* sdk = smem2 + stage * STAGE_FLOATS + 2 * KC * OUT_F;
        const int* nadj0 = adjr0 + (((t + 1) & (NTILES - 1)) << 8);  // next tile
        const int* nadj1 = adjr1 + (((t + 1) & (NTILES - 1)) << 8);

#pragma unroll
        for (int step = 0; step < NSTEP; ++step) {
            const int kk = (step << 5) | lane;
            const int av0 = am0[step], av1 = am1[step];
            am0[step] = __ldg(nadj0 + (step << 5) + lane);   // prefetch tile t+1
            am1[step] = __ldg(nadj1 + (step << 5) + lane);
            const float dkv = sdk[kk];
            const uint32_t rb2 = w2b + (uint32_t)(kk << 7);
            const uint32_t rb1 = w1b + (uint32_t)(kk << 7);
            const int sx = kk & 7;

            unsigned long long s0a = 0ull, s0b = 0ull, s1a = 0ull, s1b = 0ull;
#pragma unroll
            for (int f4 = 0; f4 < 8; ++f4) {
                unsigned long long v0, v1, u;
                asm volatile("ld.shared.v2.b64 {%0, %1}, [%2];"
                             : "=l"(v0), "=l"(v1) : "r"(rb2 + (uint32_t)((f4 ^ sx) << 4)));
                const int j0 = 2 * f4, j1 = 2 * f4 + 1;
                asm("add.rn.f32x2 %0, %1, %2;" : "=l"(u) : "l"(wh1p[0][j0]), "l"(v0));
                u &= ABS2;
                asm("fma.rn.f32x2 %0, %1, %2, %0;" : "+l"(s0a) : "l"(a4L[j0]), "l"(u));
                asm("add.rn.f32x2 %0, %1, %2;" : "=l"(u) : "l"(wh1p[0][j1]), "l"(v1));
                u &= ABS2;
                asm("fma.rn.f32x2 %0, %1, %2, %0;" : "+l"(s0b) : "l"(a4L[j1]), "l"(u));
                asm("add.rn.f32x2 %0, %1, %2;" : "=l"(u) : "l"(wh1p[1][j0]), "l"(v0));
                u &= ABS2;
                asm("fma.rn.f32x2 %0, %1, %2, %0;" : "+l"(s1a) : "l"(a4L[j0]), "l"(u));
                asm("add.rn.f32x2 %0, %1, %2;" : "=l"(u) : "l"(wh1p[1][j1]), "l"(v1));
                u &= ABS2;
                asm("fma.rn.f32x2 %0, %1, %2, %0;" : "+l"(s1b) : "l"(a4L[j1]), "l"(u));
            }

            float p0, p1;
            {
                unsigned long long ts; float lo, hi, e;
                asm("add.rn.f32x2 %0, %1, %2;" : "=l"(ts) : "l"(s0a), "l"(s0b));
                asm("mov.b64 {%0, %1}, %2;" : "=f"(lo), "=f"(hi) : "l"(ts));
                e = (c0 + dkv) + (lo + hi);
                asm("ex2.approx.f32 %0, %1;" : "=f"(p0) : "f"(e));
                p0 = (av0 > 0) ? p0 : 0.f;
                asm("add.rn.f32x2 %0, %1, %2;" : "=l"(ts) : "l"(s1a), "l"(s1b));
                asm("mov.b64 {%0, %1}, %2;" : "=f"(lo), "=f"(hi) : "l"(ts));
                e = (c1 + dkv) + (lo + hi);
                asm("ex2.approx.f32 %0, %1;" : "=f"(p1) : "f"(e));
                p1 = (av1 > 0) ? p1 : 0.f;
            }
            lsum0 += p0; lsum1 += p1;
            unsigned long long p20, p21;
            asm("mov.b64 %0, {%1, %1};" : "=l"(p20) : "f"(p0));
            asm("mov.b64 %0, {%1, %1};" : "=l"(p21) : "f"(p1));

#pragma unroll
            for (int f4 = 0; f4 < 8; ++f4) {
                unsigned long long v0, v1;
                asm volatile("ld.shared.v2.b64 {%0, %1}, [%2];"
                             : "=l"(v0), "=l"(v1) : "r"(rb1 + (uint32_t)((f4 ^ sx) << 4)));
                asm("fma.rn.f32x2 %0, %1, %2, %0;" : "+l"(acc[0][2*f4])   : "l"(p20), "l"(v0));
                asm("fma.rn.f32x2 %0, %1, %2, %0;" : "+l"(acc[0][2*f4+1]) : "l"(p20), "l"(v1));
                asm("fma.rn.f32x2 %0, %1, %2, %0;" : "+l"(acc[1][2*f4])   : "l"(p21), "l"(v0));
                asm("fma.rn.f32x2 %0, %1, %2, %0;" : "+l"(acc[1][2*f4+1]) : "l"(p21), "l"(v1));
            }
        }
    }

    // ---- Epilogue: cross-lane reduce, divide, ELU ----
    float L0 = lsum0, L1 = lsum1;
#pragma unroll
    for (int o = 16; o; o >>= 1) {
        L0 += __shfl_xor_sync(0xffffffffu, L0, o);
        L1 += __shfl_xor_sync(0xffffffffu, L1, o);
    }
    __syncthreads();                       // tile stages no longer needed
    float* red = smem2 + w * (32 * 33);
#pragma unroll 1
    for (int r = 0; r < 2; ++r) {
#pragma unroll
        for (int j = 0; j < 16; ++j) {
            float lo, hi;
            asm("mov.b64 {%0, %1}, %2;" : "=f"(lo), "=f"(hi) : "l"(acc[r][j]));
            red[lane * 33 + 2 * j]     = lo;
            red[lane * 33 + 2 * j + 1] = hi;
        }
        __syncwarp();
        float tot = 0.f;
#pragma unroll 8
        for (int jj = 0; jj < 32; ++jj) tot += red[jj * 33 + lane];
        const float L = r ? L1 : L0;
        const int row = r ? row1 : row0;
        const float hv = tot / L;
        out[row * OUT_F + lane] = hv > 0.f ? hv : expm1f(hv);
        __syncwarp();
    }
}

// ---------------------------------------------------------------------------
extern "C" void kernel_launch(void* const* d_in, const int* in_sizes, int n_in,
                              void* d_out, int out_size)
{
    const float* h   = (const float*)d_in[0];
    const int*   adj = (const int*)  d_in[1];
    const float* W   = (const float*)d_in[2];
    const float* a   = (const float*)d_in[3];
    float*       out = (float*)d_out;

    gat_gemm_kernel<<<N_NODES / 16, dim3(32, 8)>>>(h, W, a);

    cudaFuncSetAttribute(gat_attn_kernel,
                         cudaFuncAttributeMaxDynamicSharedMemorySize, SMEM_BYTES);
    gat_attn_kernel<<<GRID, THREADS, SMEM_BYTES>>>(adj, a, out);
}